// round 6
// baseline (speedup 1.0000x reference)
#include <cuda_runtime.h>
#include <cstdint>

typedef unsigned long long ull;

#define NM 4
#define NB 64
#define NL 512
#define NQ 512
#define NS 26
#define NSP 28          // padded alphabet
#define NSL 32          // p-slices per model
#define PSL 16          // p states per slice
#define NTH 128         // main kernel threads
#define PTH 256         // preprocess threads

// SMEM float offsets
#define OFF_A    0
#define SZ_A     (16*584)
#define OFF_ALP  (OFF_A + SZ_A)
#define SZ_ALP   (64*516)
#define OFF_BEM  (OFF_ALP + SZ_ALP)
#define SZ_BEM   (16*NSP)
#define OFF_PI   (OFF_BEM + SZ_BEM)
#define OFF_INP  (OFF_PI + 16)
#define SZ_INP   (2*64*NSP)
#define SMEM_FLOATS (OFF_INP + SZ_INP)
#define SMEM_BYTES  (SMEM_FLOATS*4)

// ---------------- device scratch ---------------------------------------------
__device__ float g_A[NM * NQ * NQ];
__device__ float g_pi[NM * NQ];
__device__ float g_Bem[NM * NQ * NS];
__device__ float g_alpha[NM * 2 * NB * NQ];   // double buffered [m][buf][b][q]
__device__ float g_part[NM * NB * NSL];       // per-slice partial sums
__device__ int   g_ctr[NM * 32];              // padded per-model barrier counters

// ---------------- helpers ----------------------------------------------------
__device__ __forceinline__ void lds16(ull& a, ull& b, unsigned addr) {
    asm volatile("ld.shared.v2.u64 {%0, %1}, [%2];" : "=l"(a), "=l"(b) : "r"(addr));
}
__device__ __forceinline__ void fma2(ull& d, ull a, ull x) {
    asm("fma.rn.f32x2 %0, %1, %2, %0;" : "+l"(d) : "l"(a), "l"(x));
}
__device__ __forceinline__ void unpk(ull v, float& lo, float& hi) {
    unsigned a, b;
    asm("mov.b64 {%0, %1}, %2;" : "=r"(a), "=r"(b) : "l"(v));
    lo = __uint_as_float(a); hi = __uint_as_float(b);
}
__device__ __forceinline__ float psum(ull v) { float a, b; unpk(v, a, b); return a + b; }
__device__ __forceinline__ void cp_async16(float* dst, const float* src) {
    unsigned d = (unsigned)__cvta_generic_to_shared(dst);
    asm volatile("cp.async.cg.shared.global [%0], [%1], 16;" :: "r"(d), "l"(src) : "memory");
}
__device__ __forceinline__ void cp_async8(float* dst, const float* src) {
    unsigned d = (unsigned)__cvta_generic_to_shared(dst);
    asm volatile("cp.async.ca.shared.global [%0], [%1], 8;" :: "r"(d), "l"(src) : "memory");
}
#define CP_COMMIT()  asm volatile("cp.async.commit_group;" ::: "memory")
#define CP_WAIT(n)   asm volatile("cp.async.wait_group %0;" :: "n"(n) : "memory")

// grid barrier for 32 CTAs of one model (all resident: 1 CTA/SM, 128 <= 148)
__device__ __forceinline__ void gbar(int* c, int target) {
    __syncthreads();
    if (threadIdx.x == 0) {
        asm volatile("red.release.gpu.global.add.s32 [%0], 1;" :: "l"(c) : "memory");
        int v;
        do {
            asm volatile("ld.acquire.gpu.global.b32 %0, [%1];"
                         : "=r"(v) : "l"(c) : "memory");
        } while (v < target);
    }
    __syncthreads();
}

// ---------------- fused preprocessing (ONE launch) ---------------------------
// blocks [0, NM*NQ)            : softmax rows of A      (rowlen 512)
// blocks [NM*NQ, NM*NQ+NM)     : softmax rows of pi     (rowlen 512)
// blocks [NM*NQ+NM, ...+NM*NQ) : softmax rows of Bem    (rowlen 26)
// block 0 additionally resets the barrier counters.
__global__ void pre_k(const float* __restrict__ Al, const float* __restrict__ pil,
                      const float* __restrict__ eml) {
    int r = blockIdx.x;
    int tid = threadIdx.x;
    if (r == 0 && tid < NM * 32) g_ctr[tid] = 0;

    const float* x; float* y; int len;
    if (r < NM * NQ)           { x = Al  + (size_t)r * NQ; y = g_A  + (size_t)r * NQ; len = NQ; }
    else if (r < NM * NQ + NM) { int rr = r - NM * NQ;
                                 x = pil + (size_t)rr * NQ; y = g_pi + (size_t)rr * NQ; len = NQ; }
    else                       { int rr = r - NM * NQ - NM;
                                 x = eml + (size_t)rr * NS; y = g_Bem + (size_t)rr * NS; len = NS; }

    __shared__ float red[PTH];
    float mx = -1e30f;
    for (int i = tid; i < len; i += PTH) mx = fmaxf(mx, x[i]);
    red[tid] = mx; __syncthreads();
    for (int o = PTH / 2; o > 0; o >>= 1) {
        if (tid < o) red[tid] = fmaxf(red[tid], red[tid + o]);
        __syncthreads();
    }
    mx = red[0]; __syncthreads();

    float sm = 0.f;
    for (int i = tid; i < len; i += PTH) sm += expf(x[i] - mx);
    red[tid] = sm; __syncthreads();
    for (int o = PTH / 2; o > 0; o >>= 1) {
        if (tid < o) red[tid] += red[tid + o];
        __syncthreads();
    }
    float inv = 1.0f / red[0];
    for (int i = tid; i < len; i += PTH) y[i] = expf(x[i] - mx) * inv;
}

// ---------------- main persistent forward kernel -----------------------------
// grid 128 = 4 models x 32 slices; 128 threads: tid = bp*4 + pg.
// thread owns batches (bp, bp+32) and 4 p states (slice*16 + pg*4 ..+3).
__global__ void __launch_bounds__(NTH, 1)
hmm_fwd(const float* __restrict__ inputs, float* __restrict__ out) {
    const int m     = blockIdx.x >> 5;
    const int slice = blockIdx.x & 31;
    const int p0    = slice * PSL;
    const int tid   = threadIdx.x;
    const int bp    = tid >> 2;
    const int pg    = tid & 3;
    const int b0    = bp, b1 = bp + 32;

    extern __shared__ float smf[];
    float* A_s    = smf + OFF_A;
    float* alp_s  = smf + OFF_ALP;
    float* Bem_s  = smf + OFF_BEM;    // [16p][28s]
    float* pi_s   = smf + OFF_PI;
    float* inp_s  = smf + OFF_INP;    // [2][64][28]

    // ---- one-time SMEM init ----
    {
        const float* Ag = g_A + (size_t)m * NQ * NQ + p0;
        for (int i = tid; i < PSL * NQ; i += NTH) {
            int p = i >> 9, q = i & (NQ - 1);
            int c = q >> 2, rr = q & 3;
            int sp = p + (p >> 2);
            A_s[p * 584 + (c + sp) * 4 + rr] = Ag[(size_t)q * NQ + p];
        }
        for (int i = tid; i < PSL * NSP; i += NTH) {
            int p = i / NSP, s = i - p * NSP;
            Bem_s[i] = (s < NS) ? g_Bem[((size_t)m * NQ + p0 + p) * NS + s] : 0.f;
        }
        if (tid < PSL) pi_s[tid] = g_pi[m * NQ + p0 + tid];
        // zero input-buffer pads (s = 26, 27)
        if (tid < 128) {
            int buf = tid >> 6, bb = tid & 63;
            inp_s[buf * (64 * NSP) + bb * NSP + 26] = 0.f;
            inp_s[buf * (64 * NSP) + bb * NSP + 27] = 0.f;
        }
    }

    // per-thread SMEM byte addresses
    unsigned xu0 = (unsigned)__cvta_generic_to_shared(alp_s + b0 * 516);
    unsigned xu1 = (unsigned)__cvta_generic_to_shared(alp_s + b1 * 516);
    unsigned Au0, Au1, Au2, Au3;
    {
        int p = pg * 4;
        Au0 = (unsigned)__cvta_generic_to_shared(A_s + (p+0)*584 + ((p+0)+((p+0)>>2))*4);
        Au1 = (unsigned)__cvta_generic_to_shared(A_s + (p+1)*584 + ((p+1)+((p+1)>>2))*4);
        Au2 = (unsigned)__cvta_generic_to_shared(A_s + (p+2)*584 + ((p+2)+((p+2)>>2))*4);
        Au3 = (unsigned)__cvta_generic_to_shared(A_s + (p+3)*584 + ((p+3)+((p+3)>>2))*4);
    }
    unsigned Bu0 = (unsigned)__cvta_generic_to_shared(Bem_s + (pg*4+0)*NSP);
    unsigned Bu1 = (unsigned)__cvta_generic_to_shared(Bem_s + (pg*4+1)*NSP);
    unsigned Bu2 = (unsigned)__cvta_generic_to_shared(Bem_s + (pg*4+2)*NSP);
    unsigned Bu3 = (unsigned)__cvta_generic_to_shared(Bem_s + (pg*4+3)*NSP);

    const int    q_out  = p0 + pg * 4;
    float*       gal0   = g_alpha + (size_t)(m * 2 + 0) * NB * NQ;
    float*       gal1   = g_alpha + (size_t)(m * 2 + 1) * NB * NQ;
    const float* inp_m  = inputs + (size_t)m * NB * NL * NS;
    float*       part0  = g_part + (m * NB + b0) * NSL;
    float*       part1  = g_part + (m * NB + b1) * NSL;
    int*         ctr    = &g_ctr[m * 32];
    const bool   lead   = (slice == 0) && (pg == 0);
    float ll0 = 0.f, ll1 = 0.f;

    // ---- stage inputs for t=0 and t=1 (one commit group) ----
    {
        const float* s0 = inp_m;                 // t = 0
        const float* s1 = inp_m + NS;            // t = 1
        float* d0 = inp_s;                       // buf 0
        float* d1 = inp_s + 64 * NSP;            // buf 1
        #pragma unroll
        for (int j = 0; j < 7; ++j) {
            int c = j * NTH + tid;
            if (c < 832) {
                int bb = c / 13, sc = (c - bb * 13) * 2;
                cp_async8(d0 + bb * NSP + sc, s0 + (size_t)bb * (NL * NS) + sc);
                cp_async8(d1 + bb * NSP + sc, s1 + (size_t)bb * (NL * NS) + sc);
            }
        }
        CP_COMMIT(); CP_WAIT(0);
    }
    __syncthreads();

    // ---- t = 0 : alpha0 = pi * e0 ----
    {
        unsigned ib0 = (unsigned)__cvta_generic_to_shared(inp_s + b0 * NSP);
        unsigned ib1 = (unsigned)__cvta_generic_to_shared(inp_s + b1 * NSP);
        ull eA0=0,eA1=0,eA2=0,eA3=0,eB0=0,eB1=0,eB2=0,eB3=0;
        #pragma unroll
        for (int c = 0; c < 7; ++c) {
            ull x00,x01,x10,x11,a0,a1;
            lds16(x00,x01, ib0 + c*16);
            lds16(x10,x11, ib1 + c*16);
            lds16(a0,a1, Bu0 + c*16); fma2(eA0,a0,x00); fma2(eA0,a1,x01); fma2(eB0,a0,x10); fma2(eB0,a1,x11);
            lds16(a0,a1, Bu1 + c*16); fma2(eA1,a0,x00); fma2(eA1,a1,x01); fma2(eB1,a0,x10); fma2(eB1,a1,x11);
            lds16(a0,a1, Bu2 + c*16); fma2(eA2,a0,x00); fma2(eA2,a1,x01); fma2(eB2,a0,x10); fma2(eB2,a1,x11);
            lds16(a0,a1, Bu3 + c*16); fma2(eA3,a0,x00); fma2(eA3,a1,x01); fma2(eB3,a0,x10); fma2(eB3,a1,x11);
        }
        float4 o0, o1;
        o0.x = pi_s[pg*4+0]*psum(eA0); o0.y = pi_s[pg*4+1]*psum(eA1);
        o0.z = pi_s[pg*4+2]*psum(eA2); o0.w = pi_s[pg*4+3]*psum(eA3);
        o1.x = pi_s[pg*4+0]*psum(eB0); o1.y = pi_s[pg*4+1]*psum(eB1);
        o1.z = pi_s[pg*4+2]*psum(eB2); o1.w = pi_s[pg*4+3]*psum(eB3);
        *(float4*)(gal0 + (size_t)b0 * NQ + q_out) = o0;
        *(float4*)(gal0 + (size_t)b1 * NQ + q_out) = o1;
        gbar(ctr, 32);
    }

    // ---- t = 1 .. 511 ----
    #pragma unroll 1
    for (int t = 1; t < NL; ++t) {
        const float* src = (t & 1) ? gal0 : gal1;
        float*       dst = (t & 1) ? gal1 : gal0;

        // stage alpha (two q-chunks; q16 fixed per thread, bb = 2j + hi)
        {
            int q16 = tid & 63, hi = tid >> 6;
            #pragma unroll
            for (int h = 0; h < 2; ++h) {
                #pragma unroll
                for (int j = 0; j < 32; ++j) {
                    int bb = 2*j + hi;
                    cp_async16(alp_s + bb * 516 + h * 256 + q16 * 4,
                               src + (size_t)bb * NQ + h * 256 + q16 * 4);
                }
                CP_COMMIT();
            }
        }
        // stage inputs for t+1 (clamped at the end)
        {
            int tt = (t + 1 < NL) ? (t + 1) : (NL - 1);
            const float* s1 = inp_m + (size_t)tt * NS;
            float* d1 = inp_s + ((t + 1) & 1) * (64 * NSP);
            #pragma unroll
            for (int j = 0; j < 7; ++j) {
                int c = j * NTH + tid;
                if (c < 832) {
                    int bb = c / 13, sc = (c - bb * 13) * 2;
                    cp_async8(d1 + bb * NSP + sc, s1 + (size_t)bb * (NL * NS) + sc);
                }
            }
            CP_COMMIT();
        }

        ull accA0=0,accA1=0,accA2=0,accA3=0,accB0=0,accB1=0,accB2=0,accB3=0;
        CP_WAIT(2);        // alpha chunk0 + prev-step input group done
        __syncthreads();

        // emission e_t from input buffer staged last step
        float e00,e01,e02,e03,e10,e11,e12,e13;
        {
            const float* bufb = inp_s + (t & 1) * (64 * NSP);
            unsigned ib0 = (unsigned)__cvta_generic_to_shared(bufb + b0 * NSP);
            unsigned ib1 = (unsigned)__cvta_generic_to_shared(bufb + b1 * NSP);
            ull eA0=0,eA1=0,eA2=0,eA3=0,eB0=0,eB1=0,eB2=0,eB3=0;
            #pragma unroll
            for (int c = 0; c < 7; ++c) {
                ull x00,x01,x10,x11,a0,a1;
                lds16(x00,x01, ib0 + c*16);
                lds16(x10,x11, ib1 + c*16);
                lds16(a0,a1, Bu0 + c*16); fma2(eA0,a0,x00); fma2(eA0,a1,x01); fma2(eB0,a0,x10); fma2(eB0,a1,x11);
                lds16(a0,a1, Bu1 + c*16); fma2(eA1,a0,x00); fma2(eA1,a1,x01); fma2(eB1,a0,x10); fma2(eB1,a1,x11);
                lds16(a0,a1, Bu2 + c*16); fma2(eA2,a0,x00); fma2(eA2,a1,x01); fma2(eB2,a0,x10); fma2(eB2,a1,x11);
                lds16(a0,a1, Bu3 + c*16); fma2(eA3,a0,x00); fma2(eA3,a1,x01); fma2(eB3,a0,x10); fma2(eB3,a1,x11);
            }
            e00=psum(eA0); e01=psum(eA1); e02=psum(eA2); e03=psum(eA3);
            e10=psum(eB0); e11=psum(eB1); e12=psum(eB2); e13=psum(eB3);
        }

        // chunk 0: q in [0,256)
        #pragma unroll 4
        for (int c = 0; c < 64; ++c) {
            ull x00,x01,x10,x11,a0,a1;
            lds16(x00,x01, xu0 + c*16);
            lds16(x10,x11, xu1 + c*16);
            lds16(a0,a1, Au0 + c*16); fma2(accA0,a0,x00); fma2(accA0,a1,x01); fma2(accB0,a0,x10); fma2(accB0,a1,x11);
            lds16(a0,a1, Au1 + c*16); fma2(accA1,a0,x00); fma2(accA1,a1,x01); fma2(accB1,a0,x10); fma2(accB1,a1,x11);
            lds16(a0,a1, Au2 + c*16); fma2(accA2,a0,x00); fma2(accA2,a1,x01); fma2(accB2,a0,x10); fma2(accB2,a1,x11);
            lds16(a0,a1, Au3 + c*16); fma2(accA3,a0,x00); fma2(accA3,a1,x01); fma2(accB3,a0,x10); fma2(accB3,a1,x11);
        }
        CP_WAIT(1);        // alpha chunk1 done (input group t+1 still in flight)
        __syncthreads();
        // chunk 1: q in [256,512)
        #pragma unroll 4
        for (int c = 64; c < 128; ++c) {
            ull x00,x01,x10,x11,a0,a1;
            lds16(x00,x01, xu0 + c*16);
            lds16(x10,x11, xu1 + c*16);
            lds16(a0,a1, Au0 + c*16); fma2(accA0,a0,x00); fma2(accA0,a1,x01); fma2(accB0,a0,x10); fma2(accB0,a1,x11);
            lds16(a0,a1, Au1 + c*16); fma2(accA1,a0,x00); fma2(accA1,a1,x01); fma2(accB1,a0,x10); fma2(accB1,a1,x11);
            lds16(a0,a1, Au2 + c*16); fma2(accA2,a0,x00); fma2(accA2,a1,x01); fma2(accB2,a0,x10); fma2(accB2,a1,x11);
            lds16(a0,a1, Au3 + c*16); fma2(accA3,a0,x00); fma2(accA3,a1,x01); fma2(accB3,a0,x10); fma2(accB3,a1,x11);
        }

        // finalize
        float sc0 = 1.f, sc1 = 1.f;
        if ((t & 15) == 0) {             // apply deferred 1/s
            float s0 = 0.f, s1 = 0.f;
            const float4* pp0 = (const float4*)part0;
            const float4* pp1 = (const float4*)part1;
            #pragma unroll
            for (int k = 0; k < 8; ++k) {
                float4 v0 = __ldcg(pp0 + k), v1 = __ldcg(pp1 + k);
                s0 += (v0.x + v0.y) + (v0.z + v0.w);
                s1 += (v1.x + v1.y) + (v1.z + v1.w);
            }
            sc0 = 1.0f / s0; sc1 = 1.0f / s1;
            if (lead) { ll0 += logf(s0); ll1 += logf(s1); }
        }

        float4 o0, o1;
        o0.x = psum(accA0)*e00*sc0; o0.y = psum(accA1)*e01*sc0;
        o0.z = psum(accA2)*e02*sc0; o0.w = psum(accA3)*e03*sc0;
        o1.x = psum(accB0)*e10*sc1; o1.y = psum(accB1)*e11*sc1;
        o1.z = psum(accB2)*e12*sc1; o1.w = psum(accB3)*e13*sc1;
        *(float4*)(dst + (size_t)b0 * NQ + q_out) = o0;
        *(float4*)(dst + (size_t)b1 * NQ + q_out) = o1;

        if ((t & 15) == 15) {            // publish slice partial sums
            float v0 = (o0.x + o0.y) + (o0.z + o0.w);
            float v1 = (o1.x + o1.y) + (o1.z + o1.w);
            v0 += __shfl_xor_sync(0xffffffffu, v0, 1);
            v0 += __shfl_xor_sync(0xffffffffu, v0, 2);
            v1 += __shfl_xor_sync(0xffffffffu, v1, 1);
            v1 += __shfl_xor_sync(0xffffffffu, v1, 2);
            if (pg == 0) { part0[slice] = v0; part1[slice] = v1; }
        }
        gbar(ctr, 32 * (t + 1));
    }

    // ---- finalize loglik ----
    if (lead) {
        float s0 = 0.f, s1 = 0.f;
        const float4* pp0 = (const float4*)part0;
        const float4* pp1 = (const float4*)part1;
        #pragma unroll
        for (int k = 0; k < 8; ++k) {
            float4 v0 = __ldcg(pp0 + k), v1 = __ldcg(pp1 + k);
            s0 += (v0.x + v0.y) + (v0.z + v0.w);
            s1 += (v1.x + v1.y) + (v1.z + v1.w);
        }
        out[m * NB + b0] = ll0 + logf(s0);
        out[m * NB + b1] = ll1 + logf(s1);
    }
}

// ---------------- launch ------------------------------------------------------
extern "C" void kernel_launch(void* const* d_in, const int* in_sizes, int n_in,
                              void* d_out, int out_size) {
    (void)in_sizes; (void)n_in; (void)out_size;
    const float* inputs      = (const float*)d_in[0];
    const float* A_logits    = (const float*)d_in[1];
    const float* init_logits = (const float*)d_in[2];
    const float* em_logits   = (const float*)d_in[3];
    float* out = (float*)d_out;

    cudaFuncSetAttribute(hmm_fwd, cudaFuncAttributeMaxDynamicSharedMemorySize,
                         SMEM_BYTES);

    pre_k<<<NM * NQ + NM + NM * NQ, PTH>>>(A_logits, init_logits, em_logits);
    hmm_fwd<<<NM * NSL, NTH, SMEM_BYTES>>>(inputs, out);
}

// round 7
// speedup vs baseline: 1.4998x; 1.4998x over previous
#include <cuda_runtime.h>
#include <cstdint>

typedef unsigned long long ull;

#define NM 4
#define NB 64
#define NL 512
#define NQ 512
#define NS 26
#define NSP 28          // padded alphabet
#define NSL 32          // p-slices per model
#define PSL 16          // p states per slice
#define NTH 256         // main kernel threads (8 warps)
#define PTH 256         // preprocess threads

#define ASTR 520        // A_s row stride (words); row base += (p>>2)*4 swizzle
#define XSTR 516        // alpha row stride (words)

// SMEM float offsets
#define OFF_A    0
#define SZ_A     (16*ASTR + 16)
#define OFF_ALP  (OFF_A + SZ_A)
#define SZ_ALP   (64*XSTR)
#define OFF_BEM  (OFF_ALP + SZ_ALP)
#define SZ_BEM   (16*NSP)
#define OFF_PI   (OFF_BEM + SZ_BEM)
#define OFF_INP  (OFF_PI + 16)
#define SZ_INP   (2*64*NSP)
#define SMEM_FLOATS (OFF_INP + SZ_INP)
#define SMEM_BYTES  (SMEM_FLOATS*4)

// ---------------- device scratch ---------------------------------------------
__device__ float g_A[NM * NQ * NQ];
__device__ float g_pi[NM * NQ];
__device__ float g_Bem[NM * NQ * NS];
__device__ float g_alpha[NM * 2 * NB * NQ];   // double buffered [m][buf][b][q]
__device__ float g_part[NM * NB * NSL];       // per-slice partial sums
__device__ int   g_ctr[NM * 32];              // padded per-model barrier counters

// ---------------- helpers ----------------------------------------------------
__device__ __forceinline__ void lds16(ull& a, ull& b, unsigned addr) {
    asm volatile("ld.shared.v2.u64 {%0, %1}, [%2];" : "=l"(a), "=l"(b) : "r"(addr));
}
__device__ __forceinline__ void fma2(ull& d, ull a, ull x) {
    asm("fma.rn.f32x2 %0, %1, %2, %0;" : "+l"(d) : "l"(a), "l"(x));
}
__device__ __forceinline__ void unpk(ull v, float& lo, float& hi) {
    unsigned a, b;
    asm("mov.b64 {%0, %1}, %2;" : "=r"(a), "=r"(b) : "l"(v));
    lo = __uint_as_float(a); hi = __uint_as_float(b);
}
__device__ __forceinline__ float psum(ull v) { float a, b; unpk(v, a, b); return a + b; }
__device__ __forceinline__ void cp_async16(float* dst, const float* src) {
    unsigned d = (unsigned)__cvta_generic_to_shared(dst);
    asm volatile("cp.async.cg.shared.global [%0], [%1], 16;" :: "r"(d), "l"(src) : "memory");
}
__device__ __forceinline__ void cp_async8(float* dst, const float* src) {
    unsigned d = (unsigned)__cvta_generic_to_shared(dst);
    asm volatile("cp.async.ca.shared.global [%0], [%1], 8;" :: "r"(d), "l"(src) : "memory");
}
#define CP_COMMIT()  asm volatile("cp.async.commit_group;" ::: "memory")
#define CP_WAIT(n)   asm volatile("cp.async.wait_group %0;" :: "n"(n) : "memory")

// grid barrier for 32 CTAs of one model (all resident: 1 CTA/SM, 128 <= 148)
__device__ __forceinline__ void gbar(int* c, int target) {
    __syncthreads();
    if (threadIdx.x == 0) {
        asm volatile("red.release.gpu.global.add.s32 [%0], 1;" :: "l"(c) : "memory");
        int v;
        do {
            asm volatile("ld.acquire.gpu.global.b32 %0, [%1];"
                         : "=r"(v) : "l"(c) : "memory");
        } while (v < target);
    }
    __syncthreads();
}

// ---------------- fused preprocessing (ONE launch) ---------------------------
__global__ void pre_k(const float* __restrict__ Al, const float* __restrict__ pil,
                      const float* __restrict__ eml) {
    int r = blockIdx.x;
    int tid = threadIdx.x;
    if (r == 0 && tid < NM * 32) g_ctr[tid] = 0;

    const float* x; float* y; int len;
    if (r < NM * NQ)           { x = Al  + (size_t)r * NQ; y = g_A  + (size_t)r * NQ; len = NQ; }
    else if (r < NM * NQ + NM) { int rr = r - NM * NQ;
                                 x = pil + (size_t)rr * NQ; y = g_pi + (size_t)rr * NQ; len = NQ; }
    else                       { int rr = r - NM * NQ - NM;
                                 x = eml + (size_t)rr * NS; y = g_Bem + (size_t)rr * NS; len = NS; }

    __shared__ float red[PTH];
    float mx = -1e30f;
    for (int i = tid; i < len; i += PTH) mx = fmaxf(mx, x[i]);
    red[tid] = mx; __syncthreads();
    for (int o = PTH / 2; o > 0; o >>= 1) {
        if (tid < o) red[tid] = fmaxf(red[tid], red[tid + o]);
        __syncthreads();
    }
    mx = red[0]; __syncthreads();

    float sm = 0.f;
    for (int i = tid; i < len; i += PTH) sm += expf(x[i] - mx);
    red[tid] = sm; __syncthreads();
    for (int o = PTH / 2; o > 0; o >>= 1) {
        if (tid < o) red[tid] += red[tid + o];
        __syncthreads();
    }
    float inv = 1.0f / red[0];
    for (int i = tid; i < len; i += PTH) y[i] = expf(x[i] - mx) * inv;
}

// ---------------- main persistent forward kernel -----------------------------
// grid 128 = 4 models x 32 slices; 256 threads: tid = bp*8 + pg.
// thread owns batches (bp, bp+32) and 2 p rows (slice*16 + pg*2, +1).
__global__ void __launch_bounds__(NTH, 1)
hmm_fwd(const float* __restrict__ inputs, float* __restrict__ out) {
    const int m     = blockIdx.x >> 5;
    const int slice = blockIdx.x & 31;
    const int p0    = slice * PSL;
    const int tid   = threadIdx.x;
    const int bp    = tid >> 3;
    const int pg    = tid & 7;
    const int b0    = bp, b1 = bp + 32;
    const int pr0   = pg * 2, pr1 = pg * 2 + 1;

    extern __shared__ float smf[];
    float* A_s    = smf + OFF_A;      // [16][ASTR] + per-row swizzle
    float* alp_s  = smf + OFF_ALP;    // [64][XSTR]
    float* Bem_s  = smf + OFF_BEM;    // [16p][28s]
    float* pi_s   = smf + OFF_PI;
    float* inp_s  = smf + OFF_INP;    // [2][64][28]

    // ---- one-time SMEM init ----
    {
        const float* Ag = g_A + (size_t)m * NQ * NQ + p0;
        for (int i = tid; i < PSL * NQ; i += NTH) {
            int p = i >> 9, q = i & (NQ - 1);
            A_s[p * ASTR + (p >> 2) * 4 + q] = Ag[(size_t)q * NQ + p];
        }
        for (int i = tid; i < PSL * NSP; i += NTH) {
            int p = i / NSP, s = i - p * NSP;
            Bem_s[i] = (s < NS) ? g_Bem[((size_t)m * NQ + p0 + p) * NS + s] : 0.f;
        }
        if (tid < PSL) pi_s[tid] = g_pi[m * NQ + p0 + tid];
        if (tid < 128) {
            int buf = tid >> 6, bb = tid & 63;
            inp_s[buf * (64 * NSP) + bb * NSP + 26] = 0.f;
            inp_s[buf * (64 * NSP) + bb * NSP + 27] = 0.f;
        }
    }

    // per-thread SMEM byte addresses
    unsigned xu0 = (unsigned)__cvta_generic_to_shared(alp_s + b0 * XSTR);
    unsigned xu1 = (unsigned)__cvta_generic_to_shared(alp_s + b1 * XSTR);
    unsigned Au0 = (unsigned)__cvta_generic_to_shared(A_s + pr0 * ASTR + (pr0 >> 2) * 4);
    unsigned Au1 = (unsigned)__cvta_generic_to_shared(A_s + pr1 * ASTR + (pr1 >> 2) * 4);
    unsigned Bu0 = (unsigned)__cvta_generic_to_shared(Bem_s + pr0 * NSP);
    unsigned Bu1 = (unsigned)__cvta_generic_to_shared(Bem_s + pr1 * NSP);

    const int    q_out  = p0 + pg * 2;
    float*       gal0   = g_alpha + (size_t)(m * 2 + 0) * NB * NQ;
    float*       gal1   = g_alpha + (size_t)(m * 2 + 1) * NB * NQ;
    const float* inp_m  = inputs + (size_t)m * NB * NL * NS;
    float*       part0  = g_part + (m * NB + b0) * NSL;
    float*       part1  = g_part + (m * NB + b1) * NSL;
    int*         ctr    = &g_ctr[m * 32];
    const bool   lead   = (slice == 0) && (pg == 0);
    float ll0 = 0.f, ll1 = 0.f;

    // ---- stage inputs for t=0 and t=1 (one commit group) ----
    {
        const float* s0 = inp_m;
        const float* s1 = inp_m + NS;
        float* d0 = inp_s;
        float* d1 = inp_s + 64 * NSP;
        #pragma unroll
        for (int j = 0; j < 4; ++j) {
            int c = j * NTH + tid;
            if (c < 832) {
                int bb = c / 13, sc = (c - bb * 13) * 2;
                cp_async8(d0 + bb * NSP + sc, s0 + (size_t)bb * (NL * NS) + sc);
                cp_async8(d1 + bb * NSP + sc, s1 + (size_t)bb * (NL * NS) + sc);
            }
        }
        CP_COMMIT(); CP_WAIT(0);
    }
    __syncthreads();

    // ---- t = 0 : alpha0 = pi * e0 ----
    {
        unsigned ib0 = (unsigned)__cvta_generic_to_shared(inp_s + b0 * NSP);
        unsigned ib1 = (unsigned)__cvta_generic_to_shared(inp_s + b1 * NSP);
        ull e00=0,e01=0,e10=0,e11=0;
        #pragma unroll
        for (int c = 0; c < 7; ++c) {
            ull x00,x01,x10,x11,a0,a1;
            lds16(x00,x01, ib0 + c*16);
            lds16(x10,x11, ib1 + c*16);
            lds16(a0,a1, Bu0 + c*16); fma2(e00,a0,x00); fma2(e00,a1,x01); fma2(e10,a0,x10); fma2(e10,a1,x11);
            lds16(a0,a1, Bu1 + c*16); fma2(e01,a0,x00); fma2(e01,a1,x01); fma2(e11,a0,x10); fma2(e11,a1,x11);
        }
        float2 o0, o1;
        o0.x = pi_s[pr0] * psum(e00); o0.y = pi_s[pr1] * psum(e01);
        o1.x = pi_s[pr0] * psum(e10); o1.y = pi_s[pr1] * psum(e11);
        *(float2*)(gal0 + (size_t)b0 * NQ + q_out) = o0;
        *(float2*)(gal0 + (size_t)b1 * NQ + q_out) = o1;
        gbar(ctr, 32);
    }

    // ---- t = 1 .. 511 ----
    #pragma unroll 1
    for (int t = 1; t < NL; ++t) {
        const float* src = (t & 1) ? gal0 : gal1;
        float*       dst = (t & 1) ? gal1 : gal0;

        // stage alpha in 4 q-chunks of 128 (separate commit groups)
        #pragma unroll
        for (int h = 0; h < 4; ++h) {
            #pragma unroll
            for (int j = 0; j < 8; ++j) {
                int idx = j * NTH + tid;          // 0..2047
                int bb = idx >> 5;
                int q  = h * 128 + ((idx & 31) << 2);
                cp_async16(alp_s + bb * XSTR + q, src + (size_t)bb * NQ + q);
            }
            CP_COMMIT();
        }
        // stage inputs for t+1 (clamped at the end)
        {
            int tt = (t + 1 < NL) ? (t + 1) : (NL - 1);
            const float* s1 = inp_m + (size_t)tt * NS;
            float* d1 = inp_s + ((t + 1) & 1) * (64 * NSP);
            #pragma unroll
            for (int j = 0; j < 4; ++j) {
                int c = j * NTH + tid;
                if (c < 832) {
                    int bb = c / 13, sc = (c - bb * 13) * 2;
                    cp_async8(d1 + bb * NSP + sc, s1 + (size_t)bb * (NL * NS) + sc);
                }
            }
            CP_COMMIT();
        }

        // emission e_t (inputs(t) staged last iter; completed by WAIT(5))
        CP_WAIT(5);
        __syncthreads();
        float e00,e01,e10,e11;
        {
            const float* bufb = inp_s + (t & 1) * (64 * NSP);
            unsigned ib0 = (unsigned)__cvta_generic_to_shared(bufb + b0 * NSP);
            unsigned ib1 = (unsigned)__cvta_generic_to_shared(bufb + b1 * NSP);
            ull eA0=0,eA1=0,eB0=0,eB1=0;
            #pragma unroll
            for (int c = 0; c < 7; ++c) {
                ull x00,x01,x10,x11,a0,a1;
                lds16(x00,x01, ib0 + c*16);
                lds16(x10,x11, ib1 + c*16);
                lds16(a0,a1, Bu0 + c*16); fma2(eA0,a0,x00); fma2(eA0,a1,x01); fma2(eB0,a0,x10); fma2(eB0,a1,x11);
                lds16(a0,a1, Bu1 + c*16); fma2(eA1,a0,x00); fma2(eA1,a1,x01); fma2(eB1,a0,x10); fma2(eB1,a1,x11);
            }
            e00=psum(eA0); e01=psum(eA1); e10=psum(eB0); e11=psum(eB1);
        }

        // mainloop: 4 quarters of 32 c-iters, each gated on its chunk
        ull acc00=0, acc01=0, acc10=0, acc11=0;
        CP_WAIT(4); __syncthreads();
        #pragma unroll 8
        for (int c = 0; c < 32; ++c) {
            ull x00,x01,x10,x11,a00,a01,a10,a11;
            lds16(x00,x01, xu0 + c*16);
            lds16(x10,x11, xu1 + c*16);
            lds16(a00,a01, Au0 + c*16);
            lds16(a10,a11, Au1 + c*16);
            fma2(acc00,a00,x00); fma2(acc00,a01,x01);
            fma2(acc01,a10,x00); fma2(acc01,a11,x01);
            fma2(acc10,a00,x10); fma2(acc10,a01,x11);
            fma2(acc11,a10,x10); fma2(acc11,a11,x11);
        }
        CP_WAIT(3); __syncthreads();
        #pragma unroll 8
        for (int c = 32; c < 64; ++c) {
            ull x00,x01,x10,x11,a00,a01,a10,a11;
            lds16(x00,x01, xu0 + c*16);
            lds16(x10,x11, xu1 + c*16);
            lds16(a00,a01, Au0 + c*16);
            lds16(a10,a11, Au1 + c*16);
            fma2(acc00,a00,x00); fma2(acc00,a01,x01);
            fma2(acc01,a10,x00); fma2(acc01,a11,x01);
            fma2(acc10,a00,x10); fma2(acc10,a01,x11);
            fma2(acc11,a10,x10); fma2(acc11,a11,x11);
        }
        CP_WAIT(2); __syncthreads();
        #pragma unroll 8
        for (int c = 64; c < 96; ++c) {
            ull x00,x01,x10,x11,a00,a01,a10,a11;
            lds16(x00,x01, xu0 + c*16);
            lds16(x10,x11, xu1 + c*16);
            lds16(a00,a01, Au0 + c*16);
            lds16(a10,a11, Au1 + c*16);
            fma2(acc00,a00,x00); fma2(acc00,a01,x01);
            fma2(acc01,a10,x00); fma2(acc01,a11,x01);
            fma2(acc10,a00,x10); fma2(acc10,a01,x11);
            fma2(acc11,a10,x10); fma2(acc11,a11,x11);
        }
        CP_WAIT(1); __syncthreads();
        #pragma unroll 8
        for (int c = 96; c < 128; ++c) {
            ull x00,x01,x10,x11,a00,a01,a10,a11;
            lds16(x00,x01, xu0 + c*16);
            lds16(x10,x11, xu1 + c*16);
            lds16(a00,a01, Au0 + c*16);
            lds16(a10,a11, Au1 + c*16);
            fma2(acc00,a00,x00); fma2(acc00,a01,x01);
            fma2(acc01,a10,x00); fma2(acc01,a11,x01);
            fma2(acc10,a00,x10); fma2(acc10,a01,x11);
            fma2(acc11,a10,x10); fma2(acc11,a11,x11);
        }

        // finalize
        float sc0 = 1.f, sc1 = 1.f;
        if ((t & 15) == 0) {             // apply deferred 1/s
            float s0 = 0.f, s1 = 0.f;
            const float4* pp0 = (const float4*)part0;
            const float4* pp1 = (const float4*)part1;
            #pragma unroll
            for (int k = 0; k < 8; ++k) {
                float4 v0 = __ldcg(pp0 + k), v1 = __ldcg(pp1 + k);
                s0 += (v0.x + v0.y) + (v0.z + v0.w);
                s1 += (v1.x + v1.y) + (v1.z + v1.w);
            }
            sc0 = 1.0f / s0; sc1 = 1.0f / s1;
            if (lead) { ll0 += logf(s0); ll1 += logf(s1); }
        }

        float2 o0, o1;
        o0.x = psum(acc00)*e00*sc0; o0.y = psum(acc01)*e01*sc0;
        o1.x = psum(acc10)*e10*sc1; o1.y = psum(acc11)*e11*sc1;
        *(float2*)(dst + (size_t)b0 * NQ + q_out) = o0;
        *(float2*)(dst + (size_t)b1 * NQ + q_out) = o1;

        if ((t & 15) == 15) {            // publish slice partial sums (8 lanes/bp)
            float v0 = o0.x + o0.y;
            float v1 = o1.x + o1.y;
            v0 += __shfl_xor_sync(0xffffffffu, v0, 1);
            v0 += __shfl_xor_sync(0xffffffffu, v0, 2);
            v0 += __shfl_xor_sync(0xffffffffu, v0, 4);
            v1 += __shfl_xor_sync(0xffffffffu, v1, 1);
            v1 += __shfl_xor_sync(0xffffffffu, v1, 2);
            v1 += __shfl_xor_sync(0xffffffffu, v1, 4);
            if (pg == 0) { part0[slice] = v0; part1[slice] = v1; }
        }
        gbar(ctr, 32 * (t + 1));
    }
    CP_WAIT(0);

    // ---- finalize loglik ----
    if (lead) {
        float s0 = 0.f, s1 = 0.f;
        const float4* pp0 = (const float4*)part0;
        const float4* pp1 = (const float4*)part1;
        #pragma unroll
        for (int k = 0; k < 8; ++k) {
            float4 v0 = __ldcg(pp0 + k), v1 = __ldcg(pp1 + k);
            s0 += (v0.x + v0.y) + (v0.z + v0.w);
            s1 += (v1.x + v1.y) + (v1.z + v1.w);
        }
        out[m * NB + b0] = ll0 + logf(s0);
        out[m * NB + b1] = ll1 + logf(s1);
    }
}

// ---------------- launch ------------------------------------------------------
extern "C" void kernel_launch(void* const* d_in, const int* in_sizes, int n_in,
                              void* d_out, int out_size) {
    (void)in_sizes; (void)n_in; (void)out_size;
    const float* inputs      = (const float*)d_in[0];
    const float* A_logits    = (const float*)d_in[1];
    const float* init_logits = (const float*)d_in[2];
    const float* em_logits   = (const float*)d_in[3];
    float* out = (float*)d_out;

    cudaFuncSetAttribute(hmm_fwd, cudaFuncAttributeMaxDynamicSharedMemorySize,
                         SMEM_BYTES);

    pre_k<<<NM * NQ + NM + NM * NQ, PTH>>>(A_logits, init_logits, em_logits);
    hmm_fwd<<<NM * NSL, NTH, SMEM_BYTES>>>(inputs, out);
}

// round 8
// speedup vs baseline: 1.5039x; 1.0027x over previous
#include <cuda_runtime.h>
#include <cstdint>

typedef unsigned long long ull;

#define NM 4
#define NB 64
#define NL 512
#define NQ 512
#define NS 26
#define NSP 28          // padded alphabet
#define NSL 32          // p-slices per model
#define PSL 16          // p states per slice
#define NTH 256         // main kernel threads (8 warps)
#define PTH 256         // preprocess threads

#define ASTR 520        // A_s row stride (words); row base += (p>>2)*4 swizzle
#define XSTR 516        // alpha row stride (words)

// SMEM float offsets
#define OFF_A    0
#define SZ_A     (16*ASTR + 16)
#define OFF_ALP  (OFF_A + SZ_A)
#define SZ_ALP   (64*XSTR)
#define OFF_BEM  (OFF_ALP + SZ_ALP)
#define SZ_BEM   (16*NSP)
#define OFF_PI   (OFF_BEM + SZ_BEM)
#define OFF_INP  (OFF_PI + 16)
#define SZ_INP   (2*64*NSP)
#define SMEM_FLOATS (OFF_INP + SZ_INP)
#define SMEM_BYTES  (SMEM_FLOATS*4)

// ---------------- device scratch ---------------------------------------------
__device__ float g_A[NM * NQ * NQ];
__device__ float g_pi[NM * NQ];
__device__ float g_Bem[NM * NQ * NS];
__device__ float g_alpha[NM * 2 * NB * NQ];   // double buffered [m][buf][b][q]
__device__ float g_part[NM * NB * NSL];       // per-slice partial sums
__device__ int   g_ctr[NM * 32];              // padded per-model barrier counters

// ---------------- helpers ----------------------------------------------------
__device__ __forceinline__ void lds16(ull& a, ull& b, unsigned addr) {
    asm volatile("ld.shared.v2.u64 {%0, %1}, [%2];" : "=l"(a), "=l"(b) : "r"(addr));
}
__device__ __forceinline__ void fma2(ull& d, ull a, ull x) {
    asm("fma.rn.f32x2 %0, %1, %2, %0;" : "+l"(d) : "l"(a), "l"(x));
}
__device__ __forceinline__ void unpk(ull v, float& lo, float& hi) {
    unsigned a, b;
    asm("mov.b64 {%0, %1}, %2;" : "=r"(a), "=r"(b) : "l"(v));
    lo = __uint_as_float(a); hi = __uint_as_float(b);
}
__device__ __forceinline__ float psum(ull v) { float a, b; unpk(v, a, b); return a + b; }
__device__ __forceinline__ void cp_async16(float* dst, const float* src) {
    unsigned d = (unsigned)__cvta_generic_to_shared(dst);
    asm volatile("cp.async.cg.shared.global [%0], [%1], 16;" :: "r"(d), "l"(src) : "memory");
}
__device__ __forceinline__ void cp_async8(float* dst, const float* src) {
    unsigned d = (unsigned)__cvta_generic_to_shared(dst);
    asm volatile("cp.async.ca.shared.global [%0], [%1], 8;" :: "r"(d), "l"(src) : "memory");
}
#define CP_COMMIT()  asm volatile("cp.async.commit_group;" ::: "memory")
#define CP_WAIT(n)   asm volatile("cp.async.wait_group %0;" :: "n"(n) : "memory")

// grid barrier for 32 CTAs of one model (all resident: 1 CTA/SM, 128 <= 148)
__device__ __forceinline__ void gbar(int* c, int target) {
    __syncthreads();
    if (threadIdx.x == 0) {
        asm volatile("red.release.gpu.global.add.s32 [%0], 1;" :: "l"(c) : "memory");
        int v;
        do {
            asm volatile("ld.acquire.gpu.global.b32 %0, [%1];"
                         : "=r"(v) : "l"(c) : "memory");
        } while (v < target);
    }
    __syncthreads();
}

// ---------------- fused preprocessing (ONE launch) ---------------------------
__global__ void pre_k(const float* __restrict__ Al, const float* __restrict__ pil,
                      const float* __restrict__ eml) {
    int r = blockIdx.x;
    int tid = threadIdx.x;
    if (r == 0 && tid < NM * 32) g_ctr[tid] = 0;

    const float* x; float* y; int len;
    if (r < NM * NQ)           { x = Al  + (size_t)r * NQ; y = g_A  + (size_t)r * NQ; len = NQ; }
    else if (r < NM * NQ + NM) { int rr = r - NM * NQ;
                                 x = pil + (size_t)rr * NQ; y = g_pi + (size_t)rr * NQ; len = NQ; }
    else                       { int rr = r - NM * NQ - NM;
                                 x = eml + (size_t)rr * NS; y = g_Bem + (size_t)rr * NS; len = NS; }

    __shared__ float red[PTH];
    float mx = -1e30f;
    for (int i = tid; i < len; i += PTH) mx = fmaxf(mx, x[i]);
    red[tid] = mx; __syncthreads();
    for (int o = PTH / 2; o > 0; o >>= 1) {
        if (tid < o) red[tid] = fmaxf(red[tid], red[tid + o]);
        __syncthreads();
    }
    mx = red[0]; __syncthreads();

    float sm = 0.f;
    for (int i = tid; i < len; i += PTH) sm += expf(x[i] - mx);
    red[tid] = sm; __syncthreads();
    for (int o = PTH / 2; o > 0; o >>= 1) {
        if (tid < o) red[tid] += red[tid + o];
        __syncthreads();
    }
    float inv = 1.0f / red[0];
    for (int i = tid; i < len; i += PTH) y[i] = expf(x[i] - mx) * inv;
}

// ---------------- main persistent forward kernel -----------------------------
// grid 128 = 4 models x 32 slices; 256 threads: tid = bp*8 + pg.
// thread owns batches (bp, bp+32) and 2 p rows (slice*16 + pg*2, +1).
__global__ void __launch_bounds__(NTH, 1)
hmm_fwd(const float* __restrict__ inputs, float* __restrict__ out) {
    const int m     = blockIdx.x >> 5;
    const int slice = blockIdx.x & 31;
    const int p0    = slice * PSL;
    const int tid   = threadIdx.x;
    const int bp    = tid >> 3;
    const int pg    = tid & 7;
    const int b0    = bp, b1 = bp + 32;
    const int pr0   = pg * 2, pr1 = pg * 2 + 1;

    extern __shared__ float smf[];
    float* A_s    = smf + OFF_A;      // [16][ASTR] + per-row swizzle
    float* alp_s  = smf + OFF_ALP;    // [64][XSTR]
    float* Bem_s  = smf + OFF_BEM;    // [16p][28s]
    float* pi_s   = smf + OFF_PI;
    float* inp_s  = smf + OFF_INP;    // [2][64][28]

    // ---- one-time SMEM init ----
    {
        const float* Ag = g_A + (size_t)m * NQ * NQ + p0;
        for (int i = tid; i < PSL * NQ; i += NTH) {
            int p = i >> 9, q = i & (NQ - 1);
            A_s[p * ASTR + (p >> 2) * 4 + q] = Ag[(size_t)q * NQ + p];
        }
        for (int i = tid; i < PSL * NSP; i += NTH) {
            int p = i / NSP, s = i - p * NSP;
            Bem_s[i] = (s < NS) ? g_Bem[((size_t)m * NQ + p0 + p) * NS + s] : 0.f;
        }
        if (tid < PSL) pi_s[tid] = g_pi[m * NQ + p0 + tid];
        if (tid < 128) {
            int buf = tid >> 6, bb = tid & 63;
            inp_s[buf * (64 * NSP) + bb * NSP + 26] = 0.f;
            inp_s[buf * (64 * NSP) + bb * NSP + 27] = 0.f;
        }
    }

    // per-thread SMEM byte addresses
    unsigned xu0 = (unsigned)__cvta_generic_to_shared(alp_s + b0 * XSTR);
    unsigned xu1 = (unsigned)__cvta_generic_to_shared(alp_s + b1 * XSTR);
    unsigned Au0 = (unsigned)__cvta_generic_to_shared(A_s + pr0 * ASTR + (pr0 >> 2) * 4);
    unsigned Au1 = (unsigned)__cvta_generic_to_shared(A_s + pr1 * ASTR + (pr1 >> 2) * 4);
    unsigned Bu0 = (unsigned)__cvta_generic_to_shared(Bem_s + pr0 * NSP);
    unsigned Bu1 = (unsigned)__cvta_generic_to_shared(Bem_s + pr1 * NSP);

    const int    q_out  = p0 + pg * 2;
    float*       gal0   = g_alpha + (size_t)(m * 2 + 0) * NB * NQ;
    float*       gal1   = g_alpha + (size_t)(m * 2 + 1) * NB * NQ;
    const float* inp_m  = inputs + (size_t)m * NB * NL * NS;
    float*       part0  = g_part + (m * NB + b0) * NSL;
    float*       part1  = g_part + (m * NB + b1) * NSL;
    int*         ctr    = &g_ctr[m * 32];
    const bool   lead   = (slice == 0) && (pg == 0);
    float ll0 = 0.f, ll1 = 0.f;

    // ---- stage inputs for t=0 and t=1 (one commit group) ----
    {
        const float* s0 = inp_m;
        const float* s1 = inp_m + NS;
        float* d0 = inp_s;
        float* d1 = inp_s + 64 * NSP;
        #pragma unroll
        for (int j = 0; j < 4; ++j) {
            int c = j * NTH + tid;
            if (c < 832) {
                int bb = c / 13, sc = (c - bb * 13) * 2;
                cp_async8(d0 + bb * NSP + sc, s0 + (size_t)bb * (NL * NS) + sc);
                cp_async8(d1 + bb * NSP + sc, s1 + (size_t)bb * (NL * NS) + sc);
            }
        }
        CP_COMMIT(); CP_WAIT(0);
    }
    __syncthreads();

    // ---- t = 0 : alpha0 = pi * e0 ----
    {
        unsigned ib0 = (unsigned)__cvta_generic_to_shared(inp_s + b0 * NSP);
        unsigned ib1 = (unsigned)__cvta_generic_to_shared(inp_s + b1 * NSP);
        ull e00=0,e01=0,e10=0,e11=0;
        #pragma unroll
        for (int c = 0; c < 7; ++c) {
            ull x00,x01,x10,x11,a0,a1;
            lds16(x00,x01, ib0 + c*16);
            lds16(x10,x11, ib1 + c*16);
            lds16(a0,a1, Bu0 + c*16); fma2(e00,a0,x00); fma2(e00,a1,x01); fma2(e10,a0,x10); fma2(e10,a1,x11);
            lds16(a0,a1, Bu1 + c*16); fma2(e01,a0,x00); fma2(e01,a1,x01); fma2(e11,a0,x10); fma2(e11,a1,x11);
        }
        float2 o0, o1;
        o0.x = pi_s[pr0] * psum(e00); o0.y = pi_s[pr1] * psum(e01);
        o1.x = pi_s[pr0] * psum(e10); o1.y = pi_s[pr1] * psum(e11);
        *(float2*)(gal0 + (size_t)b0 * NQ + q_out) = o0;
        *(float2*)(gal0 + (size_t)b1 * NQ + q_out) = o1;
        gbar(ctr, 32);
    }

    // ---- t = 1 .. 511 ----
    #pragma unroll 1
    for (int t = 1; t < NL; ++t) {
        const float* src = (t & 1) ? gal0 : gal1;
        float*       dst = (t & 1) ? gal1 : gal0;

        // stage alpha in 4 q-chunks of 128 (separate commit groups)
        #pragma unroll
        for (int h = 0; h < 4; ++h) {
            #pragma unroll
            for (int j = 0; j < 8; ++j) {
                int idx = j * NTH + tid;          // 0..2047
                int bb = idx >> 5;
                int q  = h * 128 + ((idx & 31) << 2);
                cp_async16(alp_s + bb * XSTR + q, src + (size_t)bb * NQ + q);
            }
            CP_COMMIT();
        }
        // stage inputs for t+1 (clamped at the end)
        {
            int tt = (t + 1 < NL) ? (t + 1) : (NL - 1);
            const float* s1 = inp_m + (size_t)tt * NS;
            float* d1 = inp_s + ((t + 1) & 1) * (64 * NSP);
            #pragma unroll
            for (int j = 0; j < 4; ++j) {
                int c = j * NTH + tid;
                if (c < 832) {
                    int bb = c / 13, sc = (c - bb * 13) * 2;
                    cp_async8(d1 + bb * NSP + sc, s1 + (size_t)bb * (NL * NS) + sc);
                }
            }
            CP_COMMIT();
        }

        // emission e_t (inputs(t) staged last iter; completed by WAIT(5))
        CP_WAIT(5);
        __syncthreads();
        float e00,e01,e10,e11;
        {
            const float* bufb = inp_s + (t & 1) * (64 * NSP);
            unsigned ib0 = (unsigned)__cvta_generic_to_shared(bufb + b0 * NSP);
            unsigned ib1 = (unsigned)__cvta_generic_to_shared(bufb + b1 * NSP);
            ull eA0=0,eA1=0,eB0=0,eB1=0;
            #pragma unroll
            for (int c = 0; c < 7; ++c) {
                ull x00,x01,x10,x11,a0,a1;
                lds16(x00,x01, ib0 + c*16);
                lds16(x10,x11, ib1 + c*16);
                lds16(a0,a1, Bu0 + c*16); fma2(eA0,a0,x00); fma2(eA0,a1,x01); fma2(eB0,a0,x10); fma2(eB0,a1,x11);
                lds16(a0,a1, Bu1 + c*16); fma2(eA1,a0,x00); fma2(eA1,a1,x01); fma2(eB1,a0,x10); fma2(eB1,a1,x11);
            }
            e00=psum(eA0); e01=psum(eA1); e10=psum(eB0); e11=psum(eB1);
        }

        // mainloop: 4 quarters of 32 c-iters, each gated on its chunk
        ull acc00=0, acc01=0, acc10=0, acc11=0;
        CP_WAIT(4); __syncthreads();
        #pragma unroll 8
        for (int c = 0; c < 32; ++c) {
            ull x00,x01,x10,x11,a00,a01,a10,a11;
            lds16(x00,x01, xu0 + c*16);
            lds16(x10,x11, xu1 + c*16);
            lds16(a00,a01, Au0 + c*16);
            lds16(a10,a11, Au1 + c*16);
            fma2(acc00,a00,x00); fma2(acc00,a01,x01);
            fma2(acc01,a10,x00); fma2(acc01,a11,x01);
            fma2(acc10,a00,x10); fma2(acc10,a01,x11);
            fma2(acc11,a10,x10); fma2(acc11,a11,x11);
        }
        CP_WAIT(3); __syncthreads();
        #pragma unroll 8
        for (int c = 32; c < 64; ++c) {
            ull x00,x01,x10,x11,a00,a01,a10,a11;
            lds16(x00,x01, xu0 + c*16);
            lds16(x10,x11, xu1 + c*16);
            lds16(a00,a01, Au0 + c*16);
            lds16(a10,a11, Au1 + c*16);
            fma2(acc00,a00,x00); fma2(acc00,a01,x01);
            fma2(acc01,a10,x00); fma2(acc01,a11,x01);
            fma2(acc10,a00,x10); fma2(acc10,a01,x11);
            fma2(acc11,a10,x10); fma2(acc11,a11,x11);
        }
        CP_WAIT(2); __syncthreads();
        #pragma unroll 8
        for (int c = 64; c < 96; ++c) {
            ull x00,x01,x10,x11,a00,a01,a10,a11;
            lds16(x00,x01, xu0 + c*16);
            lds16(x10,x11, xu1 + c*16);
            lds16(a00,a01, Au0 + c*16);
            lds16(a10,a11, Au1 + c*16);
            fma2(acc00,a00,x00); fma2(acc00,a01,x01);
            fma2(acc01,a10,x00); fma2(acc01,a11,x01);
            fma2(acc10,a00,x10); fma2(acc10,a01,x11);
            fma2(acc11,a10,x10); fma2(acc11,a11,x11);
        }
        CP_WAIT(1); __syncthreads();
        #pragma unroll 8
        for (int c = 96; c < 128; ++c) {
            ull x00,x01,x10,x11,a00,a01,a10,a11;
            lds16(x00,x01, xu0 + c*16);
            lds16(x10,x11, xu1 + c*16);
            lds16(a00,a01, Au0 + c*16);
            lds16(a10,a11, Au1 + c*16);
            fma2(acc00,a00,x00); fma2(acc00,a01,x01);
            fma2(acc01,a10,x00); fma2(acc01,a11,x01);
            fma2(acc10,a00,x10); fma2(acc10,a01,x11);
            fma2(acc11,a10,x10); fma2(acc11,a11,x11);
        }

        // finalize
        float sc0 = 1.f, sc1 = 1.f;
        if ((t & 15) == 0) {             // apply deferred 1/s
            float s0 = 0.f, s1 = 0.f;
            const float4* pp0 = (const float4*)part0;
            const float4* pp1 = (const float4*)part1;
            #pragma unroll
            for (int k = 0; k < 8; ++k) {
                float4 v0 = __ldcg(pp0 + k), v1 = __ldcg(pp1 + k);
                s0 += (v0.x + v0.y) + (v0.z + v0.w);
                s1 += (v1.x + v1.y) + (v1.z + v1.w);
            }
            sc0 = 1.0f / s0; sc1 = 1.0f / s1;
            if (lead) { ll0 += logf(s0); ll1 += logf(s1); }
        }

        float2 o0, o1;
        o0.x = psum(acc00)*e00*sc0; o0.y = psum(acc01)*e01*sc0;
        o1.x = psum(acc10)*e10*sc1; o1.y = psum(acc11)*e11*sc1;
        *(float2*)(dst + (size_t)b0 * NQ + q_out) = o0;
        *(float2*)(dst + (size_t)b1 * NQ + q_out) = o1;

        if ((t & 15) == 15) {            // publish slice partial sums (8 lanes/bp)
            float v0 = o0.x + o0.y;
            float v1 = o1.x + o1.y;
            v0 += __shfl_xor_sync(0xffffffffu, v0, 1);
            v0 += __shfl_xor_sync(0xffffffffu, v0, 2);
            v0 += __shfl_xor_sync(0xffffffffu, v0, 4);
            v1 += __shfl_xor_sync(0xffffffffu, v1, 1);
            v1 += __shfl_xor_sync(0xffffffffu, v1, 2);
            v1 += __shfl_xor_sync(0xffffffffu, v1, 4);
            if (pg == 0) { part0[slice] = v0; part1[slice] = v1; }
        }
        gbar(ctr, 32 * (t + 1));
    }
    CP_WAIT(0);

    // ---- finalize loglik ----
    if (lead) {
        float s0 = 0.f, s1 = 0.f;
        const float4* pp0 = (const float4*)part0;
        const float4* pp1 = (const float4*)part1;
        #pragma unroll
        for (int k = 0; k < 8; ++k) {
            float4 v0 = __ldcg(pp0 + k), v1 = __ldcg(pp1 + k);
            s0 += (v0.x + v0.y) + (v0.z + v0.w);
            s1 += (v1.x + v1.y) + (v1.z + v1.w);
        }
        out[m * NB + b0] = ll0 + logf(s0);
        out[m * NB + b1] = ll1 + logf(s1);
    }
}

// ---------------- launch ------------------------------------------------------
extern "C" void kernel_launch(void* const* d_in, const int* in_sizes, int n_in,
                              void* d_out, int out_size) {
    (void)in_sizes; (void)n_in; (void)out_size;
    const float* inputs      = (const float*)d_in[0];
    const float* A_logits    = (const float*)d_in[1];
    const float* init_logits = (const float*)d_in[2];
    const float* em_logits   = (const float*)d_in[3];
    float* out = (float*)d_out;

    cudaFuncSetAttribute(hmm_fwd, cudaFuncAttributeMaxDynamicSharedMemorySize,
                         SMEM_BYTES);

    pre_k<<<NM * NQ + NM + NM * NQ, PTH>>>(A_logits, init_logits, em_logits);
    hmm_fwd<<<NM * NSL, NTH, SMEM_BYTES>>>(inputs, out);
}

// round 13
// speedup vs baseline: 3.9061x; 2.5974x over previous
#include <cuda_runtime.h>
#include <cstdint>

#define NM 4
#define NB 64
#define NL 512
#define NQ 512
#define NS 26
#define NTH 256
#define PTH 256

// SMEM byte offsets (base is 1024-aligned)
#define OFF_ALP  0            // 64 rows x 1040 B (512 bf16 + 8 pad)
#define OFF_INP  66560        // 2 bufs x 64 rows x 80 B (32 bf16 + pad)
#define OFF_PART 76800        // 4 kq x 16 p x 72 f32
#define OFF_E    95232        // 16 p x 72 f32
#define OFF_PUB  99840        // 8 x 64 f32
#define OFF_INV  101888       // 64 f32
#define SMEM_BYTES 102400

#define ALP_STR  1040         // bytes per alpha row
#define INP_STR  80           // bytes per inp row
#define PRT_PSTR 72           // f32 words per p row
#define PRT_KSTR 1152         // f32 words per kq block (16*72)

// ---------------- device scratch ---------------------------------------------
__device__ float g_A[NM * NQ * NQ];
__device__ float g_pi[NM * NQ];
__device__ float g_Bem[NM * NQ * NS];
__device__ unsigned short g_alphab[NM * 2 * NB * NQ];  // bf16 alpha, dbl-buffered
__device__ float g_part[NM * NB * 32];                 // per-slice partial sums
__device__ int   g_ctr[NM * 32];

// ---------------- helpers ----------------------------------------------------
__device__ __forceinline__ uint32_t smem_u32(const void* p) {
    uint32_t a;
    asm("{ .reg .u64 t; cvta.to.shared.u64 t, %1; cvt.u32.u64 %0, t; }" : "=r"(a) : "l"(p));
    return a;
}
__device__ __forceinline__ void cp16(uint32_t dst, const void* src) {
    asm volatile("cp.async.cg.shared.global [%0], [%1], 16;" :: "r"(dst), "l"(src) : "memory");
}
#define CP_COMMIT()  asm volatile("cp.async.commit_group;" ::: "memory")
#define CP_WAIT0()   asm volatile("cp.async.wait_group 0;" ::: "memory")

__device__ __forceinline__ unsigned packbf(float lo, float hi) {
    unsigned r;
    asm("cvt.rn.bf16x2.f32 %0, %1, %2;" : "=r"(r) : "f"(hi), "f"(lo));
    return r;
}
__device__ __forceinline__ float bf2f(unsigned short u) {
    return __uint_as_float(((unsigned)u) << 16);
}
__device__ __forceinline__ void mma16816(float* d, const uint32_t* a,
                                         uint32_t b0, uint32_t b1) {
    asm volatile(
        "mma.sync.aligned.m16n8k16.row.col.f32.bf16.bf16.f32 "
        "{%0,%1,%2,%3}, {%4,%5,%6,%7}, {%8,%9}, {%0,%1,%2,%3};"
        : "+f"(d[0]), "+f"(d[1]), "+f"(d[2]), "+f"(d[3])
        : "r"(a[0]), "r"(a[1]), "r"(a[2]), "r"(a[3]), "r"(b0), "r"(b1));
}
__device__ __forceinline__ uint32_t lds32(uint32_t addr) {
    uint32_t v;
    asm volatile("ld.shared.b32 %0, [%1];" : "=r"(v) : "r"(addr) : "memory");
    return v;
}
__device__ __forceinline__ void lds64f(float& x, float& y, uint32_t addr) {
    asm volatile("ld.shared.v2.f32 {%0,%1}, [%2];" : "=f"(x), "=f"(y) : "r"(addr) : "memory");
}
__device__ __forceinline__ void sts64f(uint32_t addr, float x, float y) {
    asm volatile("st.shared.v2.f32 [%0], {%1,%2};" :: "r"(addr), "f"(x), "f"(y) : "memory");
}
__device__ __forceinline__ void sts32(uint32_t addr, uint32_t v) {
    asm volatile("st.shared.b32 [%0], %1;" :: "r"(addr), "r"(v) : "memory");
}

// grid barrier: 32 CTAs of one model (all resident; 128 CTAs <= 148 SMs).
// Every thread fences its own global writes to GPU scope BEFORE arriving.
__device__ __forceinline__ void gbar(int* c, int target) {
    __threadfence();                 // membar.gl: own STG -> gpu scope
    __syncthreads();
    if (threadIdx.x == 0) {
        asm volatile("red.release.gpu.global.add.s32 [%0], 1;" :: "l"(c) : "memory");
        int v;
        do {
            asm volatile("ld.acquire.gpu.global.b32 %0, [%1];" : "=r"(v) : "l"(c) : "memory");
        } while (v < target);
    }
    __syncthreads();
}

// ---------------- fused preprocessing ----------------------------------------
__global__ void pre_k(const float* __restrict__ Al, const float* __restrict__ pil,
                      const float* __restrict__ eml) {
    int r = blockIdx.x, tid = threadIdx.x;
    if (r == 0) {
        if (tid < NM * 32) g_ctr[tid] = 0;
        for (int i = tid; i < NM * NB * 32; i += PTH) g_part[i] = 0.f;
    }
    const float* x; float* y; int len;
    if (r < NM * NQ)           { x = Al  + (size_t)r * NQ; y = g_A  + (size_t)r * NQ; len = NQ; }
    else if (r < NM * NQ + NM) { int rr = r - NM * NQ;
                                 x = pil + (size_t)rr * NQ; y = g_pi + (size_t)rr * NQ; len = NQ; }
    else                       { int rr = r - NM * NQ - NM;
                                 x = eml + (size_t)rr * NS; y = g_Bem + (size_t)rr * NS; len = NS; }
    __shared__ float red[PTH];
    float mx = -1e30f;
    for (int i = tid; i < len; i += PTH) mx = fmaxf(mx, x[i]);
    red[tid] = mx; __syncthreads();
    for (int o = PTH / 2; o > 0; o >>= 1) {
        if (tid < o) red[tid] = fmaxf(red[tid], red[tid + o]);
        __syncthreads();
    }
    mx = red[0]; __syncthreads();
    float sm = 0.f;
    for (int i = tid; i < len; i += PTH) sm += expf(x[i] - mx);
    red[tid] = sm; __syncthreads();
    for (int o = PTH / 2; o > 0; o >>= 1) {
        if (tid < o) red[tid] += red[tid + o];
        __syncthreads();
    }
    float inv = 1.0f / red[0];
    for (int i = tid; i < len; i += PTH) y[i] = expf(x[i] - mx) * inv;
}

// ---------------- main persistent kernel --------------------------------------
// grid 128 = 4 models x 32 slices (16 p each); 256 threads = 8 warps:
// warp wid = nh*4 + kq: nh in {0,1} = 32-batch half, kq in {0..3} = 128-q quarter.
__global__ void __launch_bounds__(NTH, 1)
hmm_fwd(const float* __restrict__ inputs, float* __restrict__ out) {
    const int m     = blockIdx.x >> 5;
    const int slice = blockIdx.x & 31;
    const int p0    = slice * 16;
    const int tid   = threadIdx.x;
    const int wid   = tid >> 5;
    const int lane  = tid & 31;
    const int g     = lane >> 2;     // fragment group id
    const int t4    = lane & 3;      // thread in group
    const int nh    = wid >> 2;
    const int kq    = wid & 3;

    extern __shared__ __align__(1024) char smc[];
    const uint32_t su     = smem_u32(smc);
    const uint32_t alp_u  = su + OFF_ALP;
    const uint32_t inp_u  = su + OFF_INP;
    const uint32_t part_u = su + OFF_PART;
    const uint32_t e_u    = su + OFF_E;

    // ---- persistent A fragments (A_sl[p][q] = g_A[m][q][p0+p]) ----
    uint32_t af[8][4];
    {
        const float* Ag = g_A + (size_t)m * NQ * NQ;
        #pragma unroll
        for (int kk = 0; kk < 8; ++kk) {
            int q0 = kq * 128 + kk * 16;
            af[kk][0] = packbf(__ldg(Ag + (size_t)(q0 + 2*t4) * NQ + p0 + g),
                               __ldg(Ag + (size_t)(q0 + 2*t4 + 1) * NQ + p0 + g));
            af[kk][1] = packbf(__ldg(Ag + (size_t)(q0 + 2*t4) * NQ + p0 + g + 8),
                               __ldg(Ag + (size_t)(q0 + 2*t4 + 1) * NQ + p0 + g + 8));
            af[kk][2] = packbf(__ldg(Ag + (size_t)(q0 + 8 + 2*t4) * NQ + p0 + g),
                               __ldg(Ag + (size_t)(q0 + 9 + 2*t4) * NQ + p0 + g));
            af[kk][3] = packbf(__ldg(Ag + (size_t)(q0 + 8 + 2*t4) * NQ + p0 + g + 8),
                               __ldg(Ag + (size_t)(q0 + 9 + 2*t4) * NQ + p0 + g + 8));
        }
    }
    // ---- Bem fragments for emission HMMA (kq==0 warps only) ----
    uint32_t bem[2][4];
    if (kq == 0) {
        #pragma unroll
        for (int kk = 0; kk < 2; ++kk) {
            int s0 = kk * 16;
            auto gB = [&](int p, int s) -> float {
                return (s < NS) ? g_Bem[((size_t)m * NQ + p0 + p) * NS + s] : 0.f;
            };
            bem[kk][0] = packbf(gB(g, s0 + 2*t4),     gB(g, s0 + 2*t4 + 1));
            bem[kk][1] = packbf(gB(g + 8, s0 + 2*t4), gB(g + 8, s0 + 2*t4 + 1));
            bem[kk][2] = packbf(gB(g, s0 + 8 + 2*t4), gB(g, s0 + 9 + 2*t4));
            bem[kk][3] = packbf(gB(g + 8, s0 + 8 + 2*t4), gB(g + 8, s0 + 9 + 2*t4));
        }
    }

    // zero inp buffers (pads must be zero), THEN sync before staging data.
    for (int i = tid; i < 2560; i += NTH) sts32(inp_u + i * 4, 0u);
    __syncthreads();   // <<< FIX: order zeroing before stage_inp data stores

    const float* inp_m = inputs + (size_t)m * NB * NL * NS;
    int* ctr = &g_ctr[m * 32];
    unsigned short* gA0 = g_alphab + (size_t)(m * 2 + 0) * NB * NQ;
    unsigned short* gA1 = g_alphab + (size_t)(m * 2 + 1) * NB * NQ;

    // reduction/epilogue cell mapping: thread owns p pair, b pair
    const int pc = (tid & 7) * 2;
    const int bc = (tid >> 3) * 2;
    float ll = 0.f;

    // stage inputs for step t into bf16 tile [buf] (writes only data words k<13)
    auto stage_inp = [&](int t, int buf) {
        #pragma unroll
        for (int j = 0; j < 4; ++j) {
            int idx = j * NTH + tid;
            if (idx < 832) {
                int b = idx / 13, k = idx - b * 13;
                float2 v = __ldg((const float2*)(inp_m + (size_t)b * NL * NS +
                                                 (size_t)t * NS + k * 2));
                sts32(inp_u + buf * 5120 + b * INP_STR + k * 4, packbf(v.x, v.y));
            }
        }
    };

    // ---- t = 0 : alpha0 = pi * e0 (SIMT, one-time) ----
    stage_inp(0, 0);
    stage_inp(1, 1);
    __syncthreads();
    {
        float e[2][2] = {{0.f, 0.f}, {0.f, 0.f}};
        for (int s = 0; s < NS; ++s) {
            float B0 = g_Bem[((size_t)m * NQ + p0 + pc) * NS + s];
            float B1 = g_Bem[((size_t)m * NQ + p0 + pc + 1) * NS + s];
            #pragma unroll
            for (int j = 0; j < 2; ++j) {
                unsigned short u = *(unsigned short*)(smc + OFF_INP + (bc + j) * INP_STR + s * 2);
                float x = bf2f(u);
                e[0][j] += B0 * x; e[1][j] += B1 * x;
            }
        }
        float pi0 = g_pi[m * NQ + p0 + pc], pi1 = g_pi[m * NQ + p0 + pc + 1];
        #pragma unroll
        for (int j = 0; j < 2; ++j) {
            unsigned pk = packbf(pi0 * e[0][j], pi1 * e[1][j]);
            *(unsigned*)(gA0 + (size_t)(bc + j) * NQ + p0 + pc) = pk;
        }
    }
    gbar(ctr, 32);

    // ---- t = 1 .. 511 ----
    #pragma unroll 1
    for (int t = 1; t < NL; ++t) {
        const int dstb = t & 1;
        const unsigned short* srcg = dstb ? gA0 : gA1;
        unsigned short*       dstg = dstb ? gA1 : gA0;
        const bool resc = (t & 15) == 0;
        const bool pub  = (t & 15) == 15;

        // 1) stage alpha(t-1) into SMEM (bf16, 64 KB), async
        #pragma unroll
        for (int k = 0; k < 16; ++k) {
            int idx = k * NTH + tid;
            int b = idx >> 6, o = idx & 63;
            cp16(alp_u + b * ALP_STR + o * 16, srcg + (size_t)b * NQ + o * 8);
        }
        CP_COMMIT();

        // 2) stage inputs for t+1 (consumed next iteration)
        stage_inp(t + 1 < NL ? t + 1 : NL - 1, (t + 1) & 1);

        // 3) deferred rescale factors
        if (resc && tid < NB) {
            float s = 0.f;
            const float4* pp = (const float4*)&g_part[(m * NB + tid) * 32];
            #pragma unroll
            for (int k = 0; k < 8; ++k) {
                float4 v = __ldcg(pp + k);
                s += (v.x + v.y) + (v.z + v.w);
            }
            *(float*)(smc + OFF_INV + tid * 4) = 1.0f / s;
            if (slice == 0) ll += logf(s);
        }

        // 4) emission HMMA (kq==0 warps; inp(t) staged last iteration)
        if (kq == 0) {
            float ea[16];
            #pragma unroll
            for (int i = 0; i < 16; ++i) ea[i] = 0.f;
            uint32_t ibase = inp_u + (t & 1) * 5120 + (nh * 32 + g) * INP_STR + t4 * 4;
            #pragma unroll
            for (int nt = 0; nt < 4; ++nt) {
                uint32_t ba = ibase + nt * 8 * INP_STR;
                #pragma unroll
                for (int kk = 0; kk < 2; ++kk) {
                    uint32_t b0 = lds32(ba + kk * 32);
                    uint32_t b1 = lds32(ba + kk * 32 + 16);
                    mma16816(ea + nt * 4, bem[kk], b0, b1);
                }
            }
            #pragma unroll
            for (int nt = 0; nt < 4; ++nt) {
                uint32_t wbase = e_u + (g * PRT_PSTR + nh * 32 + nt * 8 + t4 * 2) * 4;
                sts64f(wbase, ea[nt * 4 + 0], ea[nt * 4 + 1]);
                sts64f(wbase + 8 * PRT_PSTR * 4, ea[nt * 4 + 2], ea[nt * 4 + 3]);
            }
        }

        CP_WAIT0();
        __syncthreads();

        // 5) main HMMA: D partial over this warp's 128-q quarter
        {
            float da[16];
            #pragma unroll
            for (int i = 0; i < 16; ++i) da[i] = 0.f;
            uint32_t bbase = alp_u + (nh * 32 + g) * ALP_STR + kq * 256 + t4 * 4;
            #pragma unroll
            for (int nt = 0; nt < 4; ++nt) {
                uint32_t ba = bbase + nt * 8 * ALP_STR;
                #pragma unroll
                for (int kk = 0; kk < 8; ++kk) {
                    uint32_t b0 = lds32(ba + kk * 32);
                    uint32_t b1 = lds32(ba + kk * 32 + 16);
                    mma16816(da + nt * 4, af[kk], b0, b1);
                }
            }
            #pragma unroll
            for (int nt = 0; nt < 4; ++nt) {
                uint32_t wbase = part_u +
                    (kq * PRT_KSTR + g * PRT_PSTR + nh * 32 + nt * 8 + t4 * 2) * 4;
                sts64f(wbase, da[nt * 4 + 0], da[nt * 4 + 1]);
                sts64f(wbase + 8 * PRT_PSTR * 4, da[nt * 4 + 2], da[nt * 4 + 3]);
            }
        }
        __syncthreads();

        // 6) reduce 4 kq partials, multiply emission (+1/s), store bf16 alpha
        {
            float val[2][2];
            #pragma unroll
            for (int i = 0; i < 2; ++i) {
                float d0 = 0.f, d1 = 0.f, x, y;
                #pragma unroll
                for (int k2 = 0; k2 < 4; ++k2) {
                    lds64f(x, y, part_u + (k2 * PRT_KSTR + (pc + i) * PRT_PSTR + bc) * 4);
                    d0 += x; d1 += y;
                }
                lds64f(x, y, e_u + ((pc + i) * PRT_PSTR + bc) * 4);
                val[i][0] = d0 * x; val[i][1] = d1 * y;
            }
            if (resc) {
                float i0 = *(float*)(smc + OFF_INV + bc * 4);
                float i1 = *(float*)(smc + OFF_INV + bc * 4 + 4);
                val[0][0] *= i0; val[1][0] *= i0;
                val[0][1] *= i1; val[1][1] *= i1;
            }
            #pragma unroll
            for (int j = 0; j < 2; ++j) {
                unsigned pk = packbf(val[0][j], val[1][j]);
                *(unsigned*)(dstg + (size_t)(bc + j) * NQ + p0 + pc) = pk;
            }
            if (pub) {
                #pragma unroll
                for (int j = 0; j < 2; ++j)
                    *(float*)(smc + OFF_PUB + ((tid & 7) * 64 + bc + j) * 4) =
                        val[0][j] + val[1][j];
                __syncthreads();
                if (tid < NB) {
                    float s = 0.f;
                    #pragma unroll
                    for (int k = 0; k < 8; ++k)
                        s += *(float*)(smc + OFF_PUB + (k * 64 + tid) * 4);
                    g_part[(m * NB + tid) * 32 + slice] = s;
                }
            }
        }
        gbar(ctr, 32 * (t + 1));
    }

    // ---- finalize loglik ----
    if (slice == 0 && tid < NB) {
        float s = 0.f;
        const float4* pp = (const float4*)&g_part[(m * NB + tid) * 32];
        #pragma unroll
        for (int k = 0; k < 8; ++k) {
            float4 v = __ldcg(pp + k);
            s += (v.x + v.y) + (v.z + v.w);
        }
        out[m * NB + tid] = ll + logf(s);
    }
}

// ---------------- launch ------------------------------------------------------
extern "C" void kernel_launch(void* const* d_in, const int* in_sizes, int n_in,
                              void* d_out, int out_size) {
    (void)in_sizes; (void)n_in; (void)out_size;
    const float* inputs      = (const float*)d_in[0];
    const float* A_logits    = (const float*)d_in[1];
    const float* init_logits = (const float*)d_in[2];
    const float* em_logits   = (const float*)d_in[3];
    float* out = (float*)d_out;

    cudaFuncSetAttribute(hmm_fwd, cudaFuncAttributeMaxDynamicSharedMemorySize,
                         SMEM_BYTES);

    pre_k<<<NM * NQ + NM + NM * NQ, PTH>>>(A_logits, init_logits, em_logits);
    hmm_fwd<<<NM * 32, NTH, SMEM_BYTES>>>(inputs, out);
}